// round 7
// baseline (speedup 1.0000x reference)
#include <cuda_runtime.h>
#include <stdint.h>

#define GOLDEN 0x9E3779B9u
#define OUT_MASK22 0x3FFFFFu

static const int F_FIX    = 8192;
static const int NBIN_FIX = 63;

// 4-ary search tree: 21 float4 nodes per feature (1 root + 4 L1 + 16 leaves).
// node0          : pivots a[15], a[31], a[47]
// node 1+t0      : pivots a[16*t0 + {3,7,11}]
// node 5+4*t0+t1 : leaf values a[16*t0 + 4*t1 + {0,1,2}]
// rank = 16*t0 + 4*t1 + t2  (t = count of node entries < val; +INF pad is inert)
__device__ float4   g_tree[F_FIX * 21];
__device__ unsigned g_ids_ok;   // feature_ids == arange(F_FIX)
__device__ unsigned g_key64;    // 1 if int arrays are 64-bit

__global__ void init_flags_k() { g_ids_ok = 1u; g_key64 = 1u; }

// Keys are in [0, 2^14). If stored as int64 (little endian), odd 32-bit words
// are all zero. If int32, odd words are random keys -> nonzero w.h.p.
// Sample pairs strided across the whole buffer to avoid prefix pathologies.
__global__ void detect_k(const unsigned* __restrict__ w, int npairs,
                         long long stride) {
    int i = blockIdx.x * blockDim.x + threadIdx.x;
    if (i >= npairs) return;
    long long p = (long long)i * stride;          // pair index < nnz/2
    if (w[2 * p + 1] != 0u) atomicExch(&g_key64, 0u);
}

__device__ __forceinline__ long long ld_i64(const void* p, long long i, bool w64) {
    return w64 ? ((const long long*)p)[i] : (long long)((const int*)p)[i];
}

__global__ void build_tree_k(const void* __restrict__ fids,
                             const float* __restrict__ bins) {
    int f = blockIdx.x * blockDim.x + threadIdx.x;
    if (f >= F_FIX) return;
    bool w64 = (g_key64 != 0u);
    if (ld_i64(fids, f, w64) != (long long)f) atomicExch(&g_ids_ok, 0u);
    const float* a = bins + (size_t)f * NBIN_FIX;
    float4* T = g_tree + f * 21;
    const float INF = __int_as_float(0x7f800000);
    T[0] = make_float4(a[15], a[31], a[47], INF);
#pragma unroll
    for (int t0 = 0; t0 < 4; t0++) {
        int s = 16 * t0;
        T[1 + t0] = make_float4(a[s + 3], a[s + 7], a[s + 11], INF);
#pragma unroll
        for (int t1 = 0; t1 < 4; t1++) {
            int b = s + 4 * t1;
            T[5 + 4 * t0 + t1] = make_float4(a[b], a[b + 1], a[b + 2], INF);
        }
    }
}

__device__ __forceinline__ float hash_key(long long key, unsigned bin) {
    unsigned k32 = (unsigned)(unsigned long long)key;
    unsigned h = (k32 * GOLDEN + bin) * GOLDEN;
    return (float)(h & OUT_MASK22);
}

// Fast path: feature_ids verified arange(F_FIX); bins via 3 x LDG.128.
__device__ __forceinline__ void fast_one(long long key, float v,
                                         float& ok, float& ov) {
    if ((unsigned long long)key < (unsigned long long)F_FIX) {
        const float4* T = g_tree + (int)key * 21;
        float4 n0 = T[0];
        int t0 = (n0.x < v) + (n0.y < v) + (n0.z < v);
        float4 n1 = T[1 + t0];
        int t1 = (n1.x < v) + (n1.y < v) + (n1.z < v);
        float4 n2 = T[5 + 4 * t0 + t1];
        int t2 = (n2.x < v) + (n2.y < v) + (n2.z < v);
        unsigned bin = (unsigned)(16 * t0 + 4 * t1 + t2);
        ok = hash_key(key, bin);
        ov = 1.0f;
    } else {
        ok = (float)(unsigned)(key & (long long)OUT_MASK22);
        ov = v;
    }
}

// Generic path: exact reference semantics for arbitrary sorted feature_ids.
__device__ __forceinline__ void generic_one(long long key, float v,
                                            const void* __restrict__ fids,
                                            const float* __restrict__ bins,
                                            int F, int nbin, bool w64,
                                            float& ok, float& ov) {
    int lo = 0, hi = F;                      // searchsorted left
    while (lo < hi) {
        int mid = (lo + hi) >> 1;
        if (ld_i64(fids, mid, w64) < key) lo = mid + 1; else hi = mid;
    }
    int idxs = lo < F - 1 ? lo : F - 1;
    bool cal = (ld_i64(fids, idxs, w64) == key);
    if (cal) {
        const float* row = bins + (size_t)idxs * nbin;
        int l2 = 0, h2 = nbin;               // lower bound: count(row < v)
        while (l2 < h2) {
            int m = (l2 + h2) >> 1;
            if (row[m] < v) l2 = m + 1; else h2 = m;
        }
        ok = hash_key(key, (unsigned)l2);
        ov = 1.0f;
    } else {
        ok = (float)(unsigned)(key & (long long)OUT_MASK22);
        ov = v;
    }
}

__global__ void __launch_bounds__(256) hd_main_k(
    const void* __restrict__ keys, const float* __restrict__ vals,
    const void* __restrict__ fids, const float* __restrict__ bins,
    float* __restrict__ out, int nnz, int F, int nbin, int fast_hint) {
    long long i0 = ((long long)blockIdx.x * blockDim.x + threadIdx.x) * 4;
    if (i0 >= nnz) return;
    bool w64  = (g_key64 != 0u);
    bool fast = fast_hint && (g_ids_ok != 0u);

    if (i0 + 4 <= nnz) {
        long long k4[4];
        if (w64) {
            longlong2 ka = ((const longlong2*)keys)[i0 >> 1];
            longlong2 kb = ((const longlong2*)keys)[(i0 >> 1) + 1];
            k4[0] = ka.x; k4[1] = ka.y; k4[2] = kb.x; k4[3] = kb.y;
        } else {
            int4 ki = ((const int4*)keys)[i0 >> 2];
            k4[0] = ki.x; k4[1] = ki.y; k4[2] = ki.z; k4[3] = ki.w;
        }
        float4 vv = ((const float4*)vals)[i0 >> 2];
        float v4[4] = {vv.x, vv.y, vv.z, vv.w};
        float ok[4], ov[4];
        if (fast) {
#pragma unroll
            for (int j = 0; j < 4; j++) fast_one(k4[j], v4[j], ok[j], ov[j]);
        } else {
            for (int j = 0; j < 4; j++)
                generic_one(k4[j], v4[j], fids, bins, F, nbin, w64, ok[j], ov[j]);
        }
        *(float4*)(out + i0) = make_float4(ok[0], ok[1], ok[2], ok[3]);
        float* outv = out + nnz;
        if ((nnz & 3) == 0) {
            *(float4*)(outv + i0) = make_float4(ov[0], ov[1], ov[2], ov[3]);
        } else {
#pragma unroll
            for (int j = 0; j < 4; j++) outv[i0 + j] = ov[j];
        }
    } else {
        for (long long i = i0; i < nnz; i++) {
            float ok, ov;
            long long k = ld_i64(keys, i, w64);
            if (fast) fast_one(k, vals[i], ok, ov);
            else generic_one(k, vals[i], fids, bins, F, nbin, w64, ok, ov);
            out[i] = ok;
            out[nnz + i] = ov;
        }
    }
}

extern "C" void kernel_launch(void* const* d_in, const int* in_sizes, int n_in,
                              void* d_out, int out_size) {
    const void*  keys = d_in[0];
    const float* vals = (const float*)d_in[1];
    const void*  fids = d_in[2];
    const float* bins = (const float*)d_in[3];
    float* out = (float*)d_out;

    int nnz  = in_sizes[0];
    int F    = in_sizes[2];
    int nbin = (F > 0) ? in_sizes[3] / F : 0;

    init_flags_k<<<1, 1>>>();

    // Detect 32- vs 64-bit int serialization from the keys buffer.
    long long total_pairs = (long long)nnz / 2;
    int npairs = total_pairs > 4096 ? 4096 : (int)total_pairs;
    if (npairs > 0) {
        long long stride = total_pairs / npairs;
        if (stride < 1) stride = 1;
        detect_k<<<(npairs + 255) / 256, 256>>>((const unsigned*)keys, npairs,
                                                stride);
    }

    int fast_hint = (F == F_FIX && nbin == NBIN_FIX) ? 1 : 0;
    if (fast_hint)
        build_tree_k<<<(F_FIX + 255) / 256, 256>>>(fids, bins);

    long long nthreads = ((long long)nnz + 3) / 4;
    int blocks = (int)((nthreads + 255) / 256);
    if (blocks < 1) blocks = 1;
    hd_main_k<<<blocks, 256>>>(keys, vals, fids, bins, out, nnz, F, nbin, fast_hint);
}

// round 10
// speedup vs baseline: 1.0599x; 1.0599x over previous
#include <cuda_runtime.h>
#include <stdint.h>

#define GOLDEN 0x9E3779B9u
#define OUT_MASK22 0x3FFFFFu

static const int F_FIX      = 8192;
static const int NBIN_FIX   = 63;
static const int SUB_STRIDE = 20;   // float4 per feature: [0..3]=L1 nodes, [4..19]=leaves

// Tree split: root (3 pivots a[15],a[31],a[47]) lives in SMEM inside main kernel;
// g_sub holds level-1 nodes (pivots a[16t0+{3,7,11}]) and leaves (a[16t0+4t1+{0,1,2}]).
// rank = 16*t0 + 4*t1 + t2, each t = count(node pivots < v). +INF pad inert.
__device__ float    g_root_a[F_FIX], g_root_b[F_FIX], g_root_c[F_FIX];
__device__ float4   g_sub[F_FIX * SUB_STRIDE];
__device__ unsigned g_ids_ok;   // feature_ids == arange(F_FIX)
__device__ unsigned g_key64;    // 1 if int arrays are 64-bit

// Single block: init flags + width detect. Keys in [0,2^14): if serialized as
// int64, odd 32-bit words are all zero; if int32, they're random keys.
__global__ void detect_k(const unsigned* __restrict__ w, long long nnz) {
    __shared__ unsigned s_any;
    if (threadIdx.x == 0) s_any = 0u;
    __syncthreads();
    long long total_pairs = nnz >> 1;
    int nsamp = total_pairs < 4096 ? (int)total_pairs : 4096;
    long long stride = (nsamp > 0) ? total_pairs / nsamp : 1;
    if (stride < 1) stride = 1;
    unsigned any = 0u;
    for (int s = threadIdx.x; s < nsamp; s += blockDim.x) {
        long long p = (long long)s * stride;      // pair index < nnz/2
        any |= w[2 * p + 1];
    }
    if (any) atomicOr(&s_any, 1u);
    __syncthreads();
    if (threadIdx.x == 0) {
        g_key64 = s_any ? 0u : 1u;
        g_ids_ok = 1u;
    }
}

// Coalesced tree build: 32 features per 256-thread block via smem staging.
__global__ void build_k(const void* __restrict__ fids,
                        const float* __restrict__ bins) {
    __shared__ float sb[32 * NBIN_FIX];
    int f0 = blockIdx.x * 32;
    for (int t = threadIdx.x; t < 32 * NBIN_FIX; t += blockDim.x)
        sb[t] = bins[(size_t)f0 * NBIN_FIX + t];
    __syncthreads();
    int t = threadIdx.x;
    if (t < 32) {
        int f = f0 + t;
        bool w64 = (g_key64 != 0u);
        long long fv = w64 ? ((const long long*)fids)[f]
                           : (long long)((const int*)fids)[f];
        if (fv != (long long)f) atomicExch(&g_ids_ok, 0u);
        const float* a = sb + t * NBIN_FIX;
        g_root_a[f] = a[15]; g_root_b[f] = a[31]; g_root_c[f] = a[47];
        float4* S = g_sub + f * SUB_STRIDE;
        const float INF = __int_as_float(0x7f800000);
#pragma unroll
        for (int t0 = 0; t0 < 4; t0++) {
            int s = 16 * t0;
            S[t0] = make_float4(a[s + 3], a[s + 7], a[s + 11], INF);
#pragma unroll
            for (int t1 = 0; t1 < 4; t1++) {
                int b = s + 4 * t1;
                S[4 + 4 * t0 + t1] = make_float4(a[b], a[b + 1], a[b + 2], INF);
            }
        }
    }
}

__device__ __forceinline__ long long ld_i64(const void* p, long long i, bool w64) {
    return w64 ? ((const long long*)p)[i] : (long long)((const int*)p)[i];
}

__device__ __forceinline__ float hash_key(long long key, unsigned bin) {
    unsigned k32 = (unsigned)(unsigned long long)key;
    unsigned h = (k32 * GOLDEN + bin) * GOLDEN;
    return (float)(h & OUT_MASK22);
}

// Fast path: root from SMEM (3 scalar LDS), then 2 global float4 gathers.
__device__ __forceinline__ void fast_one_s(long long key, float v,
                                           const float* __restrict__ sa,
                                           const float* __restrict__ sb,
                                           const float* __restrict__ sc,
                                           float& ok, float& ov) {
    if ((unsigned long long)key < (unsigned long long)F_FIX) {
        int k = (int)key;
        float r0 = sa[k], r1 = sb[k], r2 = sc[k];
        int t0 = (r0 < v) + (r1 < v) + (r2 < v);
        float4 n1 = g_sub[k * SUB_STRIDE + t0];
        int t1 = (n1.x < v) + (n1.y < v) + (n1.z < v);
        float4 n2 = g_sub[k * SUB_STRIDE + 4 + 4 * t0 + t1];
        int t2 = (n2.x < v) + (n2.y < v) + (n2.z < v);
        unsigned bin = (unsigned)(16 * t0 + 4 * t1 + t2);
        ok = hash_key(key, bin);
        ov = 1.0f;
    } else {
        ok = (float)(unsigned)(key & (long long)OUT_MASK22);
        ov = v;
    }
}

// Generic path: exact reference semantics for arbitrary sorted feature_ids.
__device__ __forceinline__ void generic_one(long long key, float v,
                                            const void* __restrict__ fids,
                                            const float* __restrict__ bins,
                                            int F, int nbin, bool w64,
                                            float& ok, float& ov) {
    int lo = 0, hi = F;                      // searchsorted left
    while (lo < hi) {
        int mid = (lo + hi) >> 1;
        if (ld_i64(fids, mid, w64) < key) lo = mid + 1; else hi = mid;
    }
    int idxs = lo < F - 1 ? lo : F - 1;
    bool cal = (ld_i64(fids, idxs, w64) == key);
    if (cal) {
        const float* row = bins + (size_t)idxs * nbin;
        int l2 = 0, h2 = nbin;               // lower bound: count(row < v)
        while (l2 < h2) {
            int m = (l2 + h2) >> 1;
            if (row[m] < v) l2 = m + 1; else h2 = m;
        }
        ok = hash_key(key, (unsigned)l2);
        ov = 1.0f;
    } else {
        ok = (float)(unsigned)(key & (long long)OUT_MASK22);
        ov = v;
    }
}

extern __shared__ float s_root[];   // [3 * F_FIX]: a | b | c

__global__ void __launch_bounds__(1024, 1) hd_main_k(
    const void* __restrict__ keys, const float* __restrict__ vals,
    const void* __restrict__ fids, const float* __restrict__ bins,
    float* __restrict__ out, long long nnz, int F, int nbin, int fast_hint) {
    float* sa = s_root;
    float* sb = s_root + F_FIX;
    float* sc = s_root + 2 * F_FIX;
    bool w64  = (g_key64 != 0u);
    bool fast = fast_hint && (g_ids_ok != 0u);

    if (fast) {
        for (int t = threadIdx.x; t < F_FIX; t += blockDim.x) {
            sa[t] = g_root_a[t];
            sb[t] = g_root_b[t];
            sc[t] = g_root_c[t];
        }
    }
    __syncthreads();

    bool val_vec = ((nnz & 3) == 0);
    long long nvec = (nnz + 3) >> 2;
    long long stride = (long long)gridDim.x * blockDim.x;
    for (long long vi = (long long)blockIdx.x * blockDim.x + threadIdx.x;
         vi < nvec; vi += stride) {
        long long i0 = vi << 2;
        if (i0 + 4 <= nnz) {
            long long k4[4];
            if (w64) {
                longlong2 ka = ((const longlong2*)keys)[i0 >> 1];
                longlong2 kb = ((const longlong2*)keys)[(i0 >> 1) + 1];
                k4[0] = ka.x; k4[1] = ka.y; k4[2] = kb.x; k4[3] = kb.y;
            } else {
                int4 ki = ((const int4*)keys)[i0 >> 2];
                k4[0] = ki.x; k4[1] = ki.y; k4[2] = ki.z; k4[3] = ki.w;
            }
            float4 vv = ((const float4*)vals)[i0 >> 2];
            float v4[4] = {vv.x, vv.y, vv.z, vv.w};
            float ok[4], ov[4];
            if (fast) {
#pragma unroll
                for (int j = 0; j < 4; j++)
                    fast_one_s(k4[j], v4[j], sa, sb, sc, ok[j], ov[j]);
            } else {
                for (int j = 0; j < 4; j++)
                    generic_one(k4[j], v4[j], fids, bins, F, nbin, w64,
                                ok[j], ov[j]);
            }
            *(float4*)(out + i0) = make_float4(ok[0], ok[1], ok[2], ok[3]);
            float* outv = out + nnz;
            if (val_vec) {
                *(float4*)(outv + i0) = make_float4(ov[0], ov[1], ov[2], ov[3]);
            } else {
#pragma unroll
                for (int j = 0; j < 4; j++) outv[i0 + j] = ov[j];
            }
        } else {
            for (long long i = i0; i < nnz; i++) {
                float ok, ov;
                long long k = ld_i64(keys, i, w64);
                if (fast) fast_one_s(k, vals[i], sa, sb, sc, ok, ov);
                else generic_one(k, vals[i], fids, bins, F, nbin, w64, ok, ov);
                out[i] = ok;
                out[nnz + i] = ov;
            }
        }
    }
}

extern "C" void kernel_launch(void* const* d_in, const int* in_sizes, int n_in,
                              void* d_out, int out_size) {
    const void*  keys = d_in[0];
    const float* vals = (const float*)d_in[1];
    const void*  fids = d_in[2];
    const float* bins = (const float*)d_in[3];
    float* out = (float*)d_out;

    long long nnz = in_sizes[0];
    int F    = in_sizes[2];
    int nbin = (F > 0) ? in_sizes[3] / F : 0;
    int fast_hint = (F == F_FIX && nbin == NBIN_FIX) ? 1 : 0;

    int sms = 148;
    cudaDeviceGetAttribute(&sms, cudaDevAttrMultiProcessorCount, 0);
    if (sms < 1) sms = 148;

    static_assert(3 * F_FIX * sizeof(float) == 98304, "smem size");
    cudaFuncSetAttribute(hd_main_k, cudaFuncAttributeMaxDynamicSharedMemorySize,
                         98304);

    detect_k<<<1, 256>>>((const unsigned*)keys, nnz);
    if (fast_hint)
        build_k<<<F_FIX / 32, 256>>>(fids, bins);

    hd_main_k<<<sms, 1024, 98304>>>(keys, vals, fids, bins, out, nnz, F, nbin,
                                    fast_hint);
}

// round 12
// speedup vs baseline: 1.2100x; 1.1416x over previous
#include <cuda_runtime.h>
#include <stdint.h>

#define GOLDEN 0x9E3779B9u
#define OUT_MASK22 0x3FFFFFu

static const int F_FIX      = 8192;
static const int NBIN_FIX   = 63;
static const int SUB_STRIDE = 20;   // float4 per feature: [0..3]=L1 nodes, [4..19]=leaves

// Tree split: root (3 pivots a[15],a[31],a[47]) lives in SMEM inside main kernel;
// g_sub holds level-1 nodes (pivots a[16t0+{3,7,11}]) and leaves (a[16t0+4t1+{0,1,2}]).
// rank = 16*t0 + 4*t1 + t2, each t = count(node pivots < v). +INF pad inert.
__device__ float    g_root_a[F_FIX], g_root_b[F_FIX], g_root_c[F_FIX];
__device__ float4   g_sub[F_FIX * SUB_STRIDE];
__device__ unsigned g_ids_ok;   // feature_ids == arange(F_FIX)
__device__ unsigned g_key64;    // 1 if int arrays are 64-bit

// Width detect, COALESCED: keys in [0,2^14). If serialized as int64 (LE), odd
// 32-bit words are all zero; if int32, they're random keys. One 256-thread
// block reads two contiguous 512-word windows (front + middle) -> 2 coalesced
// loads per thread, ~2us total instead of 15.6us strided sampling.
__global__ void detect_k(const unsigned* __restrict__ w, long long nnz) {
    __shared__ unsigned s_any;
    if (threadIdx.x == 0) s_any = 0u;
    __syncthreads();
    long long tp = nnz >> 1;                 // total pairs
    int t = threadIdx.x;
    unsigned any = 0u;
    if (t < tp) any |= w[2 * t + 1];
    long long m = (tp > 256) ? (tp - 256) : 0;
    if (m + t < tp) any |= w[2 * (m + t) + 1];
    if (any) atomicOr(&s_any, 1u);
    __syncthreads();
    if (threadIdx.x == 0) {
        g_key64 = s_any ? 0u : 1u;
        g_ids_ok = 1u;
    }
}

// Coalesced tree build: 32 features per 256-thread block via smem staging.
__global__ void build_k(const void* __restrict__ fids,
                        const float* __restrict__ bins) {
    __shared__ float sb[32 * NBIN_FIX];
    int f0 = blockIdx.x * 32;
    for (int t = threadIdx.x; t < 32 * NBIN_FIX; t += blockDim.x)
        sb[t] = bins[(size_t)f0 * NBIN_FIX + t];
    __syncthreads();
    int t = threadIdx.x;
    if (t < 32) {
        int f = f0 + t;
        bool w64 = (g_key64 != 0u);
        long long fv = w64 ? ((const long long*)fids)[f]
                           : (long long)((const int*)fids)[f];
        if (fv != (long long)f) atomicExch(&g_ids_ok, 0u);
        const float* a = sb + t * NBIN_FIX;
        g_root_a[f] = a[15]; g_root_b[f] = a[31]; g_root_c[f] = a[47];
        float4* S = g_sub + f * SUB_STRIDE;
        const float INF = __int_as_float(0x7f800000);
#pragma unroll
        for (int t0 = 0; t0 < 4; t0++) {
            int s = 16 * t0;
            S[t0] = make_float4(a[s + 3], a[s + 7], a[s + 11], INF);
#pragma unroll
            for (int t1 = 0; t1 < 4; t1++) {
                int b = s + 4 * t1;
                S[4 + 4 * t0 + t1] = make_float4(a[b], a[b + 1], a[b + 2], INF);
            }
        }
    }
}

__device__ __forceinline__ long long ld_i64(const void* p, long long i, bool w64) {
    return w64 ? ((const long long*)p)[i] : (long long)((const int*)p)[i];
}

__device__ __forceinline__ float hash_key(long long key, unsigned bin) {
    unsigned k32 = (unsigned)(unsigned long long)key;
    unsigned h = (k32 * GOLDEN + bin) * GOLDEN;
    return (float)(h & OUT_MASK22);
}

// Fast path: root from SMEM (3 scalar LDS), then 2 global float4 gathers.
__device__ __forceinline__ void fast_one_s(long long key, float v,
                                           const float* __restrict__ sa,
                                           const float* __restrict__ sb,
                                           const float* __restrict__ sc,
                                           float& ok, float& ov) {
    if ((unsigned long long)key < (unsigned long long)F_FIX) {
        int k = (int)key;
        float r0 = sa[k], r1 = sb[k], r2 = sc[k];
        int t0 = (r0 < v) + (r1 < v) + (r2 < v);
        float4 n1 = g_sub[k * SUB_STRIDE + t0];
        int t1 = (n1.x < v) + (n1.y < v) + (n1.z < v);
        float4 n2 = g_sub[k * SUB_STRIDE + 4 + 4 * t0 + t1];
        int t2 = (n2.x < v) + (n2.y < v) + (n2.z < v);
        unsigned bin = (unsigned)(16 * t0 + 4 * t1 + t2);
        ok = hash_key(key, bin);
        ov = 1.0f;
    } else {
        ok = (float)(unsigned)(key & (long long)OUT_MASK22);
        ov = v;
    }
}

// Generic path: exact reference semantics for arbitrary sorted feature_ids.
__device__ __forceinline__ void generic_one(long long key, float v,
                                            const void* __restrict__ fids,
                                            const float* __restrict__ bins,
                                            int F, int nbin, bool w64,
                                            float& ok, float& ov) {
    int lo = 0, hi = F;                      // searchsorted left
    while (lo < hi) {
        int mid = (lo + hi) >> 1;
        if (ld_i64(fids, mid, w64) < key) lo = mid + 1; else hi = mid;
    }
    int idxs = lo < F - 1 ? lo : F - 1;
    bool cal = (ld_i64(fids, idxs, w64) == key);
    if (cal) {
        const float* row = bins + (size_t)idxs * nbin;
        int l2 = 0, h2 = nbin;               // lower bound: count(row < v)
        while (l2 < h2) {
            int m = (l2 + h2) >> 1;
            if (row[m] < v) l2 = m + 1; else h2 = m;
        }
        ok = hash_key(key, (unsigned)l2);
        ov = 1.0f;
    } else {
        ok = (float)(unsigned)(key & (long long)OUT_MASK22);
        ov = v;
    }
}

extern __shared__ float s_root[];   // [3 * F_FIX]: a | b | c

__global__ void __launch_bounds__(1024, 1) hd_main_k(
    const void* __restrict__ keys, const float* __restrict__ vals,
    const void* __restrict__ fids, const float* __restrict__ bins,
    float* __restrict__ out, long long nnz, int F, int nbin, int fast_hint) {
    float* sa = s_root;
    float* sb = s_root + F_FIX;
    float* sc = s_root + 2 * F_FIX;
    bool w64  = (g_key64 != 0u);
    bool fast = fast_hint && (g_ids_ok != 0u);

    if (fast) {
        for (int t = threadIdx.x; t < F_FIX; t += blockDim.x) {
            sa[t] = g_root_a[t];
            sb[t] = g_root_b[t];
            sc[t] = g_root_c[t];
        }
    }
    __syncthreads();

    bool val_vec = ((nnz & 3) == 0);
    long long nvec = (nnz + 3) >> 2;
    long long stride = (long long)gridDim.x * blockDim.x;
    for (long long vi = (long long)blockIdx.x * blockDim.x + threadIdx.x;
         vi < nvec; vi += stride) {
        long long i0 = vi << 2;
        if (i0 + 4 <= nnz) {
            long long k4[4];
            if (w64) {
                longlong2 ka = ((const longlong2*)keys)[i0 >> 1];
                longlong2 kb = ((const longlong2*)keys)[(i0 >> 1) + 1];
                k4[0] = ka.x; k4[1] = ka.y; k4[2] = kb.x; k4[3] = kb.y;
            } else {
                int4 ki = ((const int4*)keys)[i0 >> 2];
                k4[0] = ki.x; k4[1] = ki.y; k4[2] = ki.z; k4[3] = ki.w;
            }
            float4 vv = ((const float4*)vals)[i0 >> 2];
            float v4[4] = {vv.x, vv.y, vv.z, vv.w};
            float ok[4], ov[4];
            if (fast) {
#pragma unroll
                for (int j = 0; j < 4; j++)
                    fast_one_s(k4[j], v4[j], sa, sb, sc, ok[j], ov[j]);
            } else {
                for (int j = 0; j < 4; j++)
                    generic_one(k4[j], v4[j], fids, bins, F, nbin, w64,
                                ok[j], ov[j]);
            }
            *(float4*)(out + i0) = make_float4(ok[0], ok[1], ok[2], ok[3]);
            float* outv = out + nnz;
            if (val_vec) {
                *(float4*)(outv + i0) = make_float4(ov[0], ov[1], ov[2], ov[3]);
            } else {
#pragma unroll
                for (int j = 0; j < 4; j++) outv[i0 + j] = ov[j];
            }
        } else {
            for (long long i = i0; i < nnz; i++) {
                float ok, ov;
                long long k = ld_i64(keys, i, w64);
                if (fast) fast_one_s(k, vals[i], sa, sb, sc, ok, ov);
                else generic_one(k, vals[i], fids, bins, F, nbin, w64, ok, ov);
                out[i] = ok;
                out[nnz + i] = ov;
            }
        }
    }
}

extern "C" void kernel_launch(void* const* d_in, const int* in_sizes, int n_in,
                              void* d_out, int out_size) {
    const void*  keys = d_in[0];
    const float* vals = (const float*)d_in[1];
    const void*  fids = d_in[2];
    const float* bins = (const float*)d_in[3];
    float* out = (float*)d_out;

    long long nnz = in_sizes[0];
    int F    = in_sizes[2];
    int nbin = (F > 0) ? in_sizes[3] / F : 0;
    int fast_hint = (F == F_FIX && nbin == NBIN_FIX) ? 1 : 0;

    int sms = 148;
    cudaDeviceGetAttribute(&sms, cudaDevAttrMultiProcessorCount, 0);
    if (sms < 1) sms = 148;

    static_assert(3 * F_FIX * sizeof(float) == 98304, "smem size");
    cudaFuncSetAttribute(hd_main_k, cudaFuncAttributeMaxDynamicSharedMemorySize,
                         98304);

    detect_k<<<1, 256>>>((const unsigned*)keys, nnz);
    if (fast_hint)
        build_k<<<F_FIX / 32, 256>>>(fids, bins);

    hd_main_k<<<sms, 1024, 98304>>>(keys, vals, fids, bins, out, nnz, F, nbin,
                                    fast_hint);
}